// round 10
// baseline (speedup 1.0000x reference)
#include <cuda_runtime.h>

#define BB       8
#define N_SMALL  12288
#define N_FULL   24576
#define CC       256
#define KK       4096
#define SLOTS    8             // max writes tracked per vertex (Poisson(1/6))

// Global scratch (~7.6 MB). Zero-initialized at module load == empty state:
//   g_cnt == 0  : no write events bucketed
//   g_inv == 0  : "vertex not in mask" (we store image_row + 1, 0 = absent)
// The LAST kernel (gather) restores this empty state for the next replay.
__device__ int g_cnt  [BB * N_FULL];          // writes per vertex
__device__ int g_slots[BB * N_FULL * SLOTS];  // packed (p<<15)|f, unordered
__device__ int g_inv  [BB * N_FULL];          // full-vertex -> image row + 1, 0 = none
__device__ int g_row  [BB * N_FULL];          // output row -> image row, or -1

// ---------------------------------------------------------------------------
// K1: full-grid fill, 2 events (or 2 mask entries) per thread via int2 loads.
//   Reference scan at time p = 0..K-1 executes vf[T[p]] = vf[F[p]] with
//   F[p] = order[b,0,K-1-p], T[p] = order[b,1,K-1-p]. Time order is captured
//   in the packed entries, so processing order here is irrelevant.
// ---------------------------------------------------------------------------
#define EV2   (BB * KK / 2)        // 16384 event-pair threads
#define MK2   (BB * N_SMALL / 2)   // 49152 mask-pair threads

__global__ void fill_kernel(const int* __restrict__ mask_idx,
                            const int* __restrict__ order)
{
    const int t = blockIdx.x * blockDim.x + threadIdx.x;
    if (t < EV2) {
        const int b  = t / (KK / 2);
        const int k2 = (t - b * (KK / 2)) * 2;      // first order column of pair
        const int2 f2 = *(const int2*)&order[b * 2 * KK + k2];
        const int2 t2 = *(const int2*)&order[b * 2 * KK + KK + k2];

        // event 0: column k2,   time p = KK-1-k2
        {
            const int idx  = b * N_FULL + t2.x;
            const int slot = atomicAdd(&g_cnt[idx], 1);
            if (slot < SLOTS)
                __stcs(&g_slots[idx * SLOTS + slot], ((KK - 1 - k2) << 15) | f2.x);
        }
        // event 1: column k2+1, time p = KK-2-k2
        {
            const int idx  = b * N_FULL + t2.y;
            const int slot = atomicAdd(&g_cnt[idx], 1);
            if (slot < SLOTS)
                __stcs(&g_slots[idx * SLOTS + slot], ((KK - 2 - k2) << 15) | f2.y);
        }
    } else {
        const int u = t - EV2;
        if (u < MK2) {
            const int b  = u / (N_SMALL / 2);
            const int i2 = (u - b * (N_SMALL / 2)) * 2;
            const int2 m = *(const int2*)&mask_idx[b * N_SMALL + i2];
            g_inv[b * N_FULL + m.x] = i2 + 1;
            g_inv[b * N_FULL + m.y] = i2 + 2;
        }
    }
}

// ---------------------------------------------------------------------------
// K2: one thread per (b, v) — parallel provenance chase.
//   chase(v, P): among writes to v with time < P pick the latest; hop to its
//   source with the new bound; stop when none. Expected hops ~1.2.
// ---------------------------------------------------------------------------
__global__ void chase_kernel()
{
    const int t = blockIdx.x * blockDim.x + threadIdx.x;
    if (t >= BB * N_FULL) return;
    const int b    = t / N_FULL;
    const int base = b * N_FULL;

    int cur = t - base, P = KK;
    for (;;) {
        const int idx = base + cur;
        const int n   = __ldg(&g_cnt[idx]);
        int best = -1;
        for (int j = 0; j < n; j++) {
            int pv = __ldg(&g_slots[idx * SLOTS + j]);
            if ((pv >> 15) < P && pv > best) best = pv;
        }
        if (best < 0) break;
        cur = best & 0x7FFF;
        P   = best >> 15;
    }
    g_row[t] = __ldg(&g_inv[base + cur]) - 1;   // -1 = zero row
}

// ---------------------------------------------------------------------------
// K3: row gather with TWO independent chains per thread (proven R7 form).
//   Thread serves 2 float4 (32B) in each output half. A warp covers one
//   contiguous 1 KB row per segment (warp-uniform index, fully coalesced).
//   ALSO restores g_cnt/g_inv empty state for the next graph replay.
// ---------------------------------------------------------------------------
#define HALF4 (BB * N_FULL * (CC / 4) / 2)   // 6,291,456 float4 per half

__global__ void gather_kernel(const float4* __restrict__ img,
                              float4* __restrict__ out)
{
    const int t = blockIdx.x * blockDim.x + threadIdx.x;

    // restore empty scratch state for the next replay (gather reads only g_row)
    if (t < BB * N_FULL) {
        __stcs(&g_cnt[t], 0);
        __stcs(&g_inv[t], 0);
    }

    const int i4 = t * 2;                 // first float4 index (half-local)
    const int rA = i4 >> 6;               // row in first half
    const int q  = i4 & 63;               // float4 offset within row
    const int rB = rA + (BB * N_FULL / 2);

    const int rowA = __ldg(&g_row[rA]);
    const int rowB = __ldg(&g_row[rB]);

    const int bA = rA / N_FULL;
    const int bB = rB / N_FULL;

    float4 a0, a1, b0, b1;
    const float4 z = make_float4(0.f, 0.f, 0.f, 0.f);

    if (rowA >= 0) {
        const float4* s = img + ((size_t)bA * N_SMALL + rowA) * 64 + q;
        a0 = __ldg(s + 0);
        a1 = __ldg(s + 1);
    } else { a0 = a1 = z; }

    if (rowB >= 0) {
        const float4* s = img + ((size_t)bB * N_SMALL + rowB) * 64 + q;
        b0 = __ldg(s + 0);
        b1 = __ldg(s + 1);
    } else { b0 = b1 = z; }

    __stcs(out + i4 + 0, a0);
    __stcs(out + i4 + 1, a1);
    __stcs(out + HALF4 + i4 + 0, b0);
    __stcs(out + HALF4 + i4 + 1, b1);
}

extern "C" void kernel_launch(void* const* d_in, const int* in_sizes, int n_in,
                              void* d_out, int out_size)
{
    const float* images   = (const float*)d_in[0];
    const int*   mask_idx = (const int*)d_in[1];
    const int*   order    = (const int*)d_in[2];
    float* out = (float*)d_out;

    const int fill_threads = EV2 + MK2;                // 65536
    fill_kernel<<<(fill_threads + 255) / 256, 256>>>(mask_idx, order);

    chase_kernel<<<(BB * N_FULL + 255) / 256, 256>>>();

    const int nthreads = HALF4 / 2;        // 3,145,728 threads
    gather_kernel<<<nthreads / 256, 256>>>((const float4*)images, (float4*)out);
}

// round 11
// speedup vs baseline: 1.1095x; 1.1095x over previous
#include <cuda_runtime.h>

#define BB       8
#define N_SMALL  12288
#define N_FULL   24576
#define CC       256
#define KK       4096
#define SLOTS    8             // max writes tracked per vertex (Poisson(1/6))

// Global scratch (~7.6 MB). Zero-initialized at module load == empty state:
//   g_cnt == 0  : no write events bucketed
//   g_inv == 0  : "vertex not in mask" (we store image_row + 1, 0 = absent)
// The LAST kernel (gather) restores this empty state for the next replay.
__device__ int g_cnt  [BB * N_FULL];          // writes per vertex
__device__ int g_slots[BB * N_FULL * SLOTS];  // packed (p<<15)|f, unordered
__device__ int g_inv  [BB * N_FULL];          // full-vertex -> image row + 1, 0 = none
__device__ int g_row  [BB * N_FULL];          // output row -> image row, or -1

// ---------------------------------------------------------------------------
// K1: fill — bucket write events + scatter mask into inv.
//   Reference scan at time p = 0..K-1 executes vf[T[p]] = vf[F[p]] with
//   F[p] = order[b,0,K-1-p], T[p] = order[b,1,K-1-p]. Time order is captured
//   in the packed entries, so processing order here is irrelevant.
// ---------------------------------------------------------------------------
__global__ void fill_kernel(const int* __restrict__ mask_idx,
                            const int* __restrict__ order)
{
    const int t = blockIdx.x * blockDim.x + threadIdx.x;
    if (t < BB * KK) {
        const int b = t / KK;
        const int k = t - b * KK;           // order column; time p = KK-1-k
        const int f = __ldg(&order[b * 2 * KK + k]);
        const int v = __ldg(&order[b * 2 * KK + KK + k]);
        const int idx  = b * N_FULL + v;
        const int slot = atomicAdd(&g_cnt[idx], 1);
        if (slot < SLOTS)                   // overflow prob ~5e-8 per run
            __stcs(&g_slots[idx * SLOTS + slot], ((KK - 1 - k) << 15) | f);
    } else {
        const int u = t - BB * KK;
        if (u < BB * N_SMALL) {
            const int b = u / N_SMALL;
            const int i = u - b * N_SMALL;
            g_inv[b * N_FULL + __ldg(&mask_idx[u])] = i + 1;
        }
    }
}

// ---------------------------------------------------------------------------
// K2: one thread per (b, v) — parallel provenance chase.
//   chase(v, P): among writes to v with time < P pick the latest; hop to its
//   source with the new bound; stop when none. Expected hops ~1.2.
// ---------------------------------------------------------------------------
__global__ void chase_kernel()
{
    const int t = blockIdx.x * blockDim.x + threadIdx.x;
    if (t >= BB * N_FULL) return;
    const int b    = t / N_FULL;
    const int base = b * N_FULL;

    int cur = t - base, P = KK;
    for (;;) {
        const int idx = base + cur;
        const int n   = __ldg(&g_cnt[idx]);
        int best = -1;
        for (int j = 0; j < n; j++) {
            int pv = __ldg(&g_slots[idx * SLOTS + j]);
            if ((pv >> 15) < P && pv > best) best = pv;
        }
        if (best < 0) break;
        cur = best & 0x7FFF;
        P   = best >> 15;
    }
    g_row[t] = __ldg(&g_inv[base + cur]) - 1;   // -1 = zero row
}

// ---------------------------------------------------------------------------
// K3: gather with smem-staged row indices.
//   CTA = 256 threads owns 32 consecutive output rows (32 KB).
//   Step 1: 32 threads load the 32 row indices coalesced into smem.
//   Step 2: each thread serves ONE row with 8 INDEPENDENT float4 loads,
//           interleaved so each warp instruction touches contiguous 128B
//           lines (thread q = tid&7 covers float4 q + 8i).
//   Index comes from LDS (29 cyc) instead of a dependent L2 load -> the
//   8-deep data-load MLP is exposed immediately.
//   ALSO restores g_cnt/g_inv empty state for the next graph replay.
// ---------------------------------------------------------------------------
#define RPB 32                               // rows per block

__global__ void __launch_bounds__(256, 4)
gather_kernel(const float4* __restrict__ img,
              float4* __restrict__ out)
{
    __shared__ int srow[RPB];

    const int tid     = threadIdx.x;
    const int rowBase = blockIdx.x * RPB;

    if (tid < RPB) srow[tid] = __ldg(&g_row[rowBase + tid]);

    // restore empty scratch state for the next replay (reads only g_row)
    const int gt = blockIdx.x * blockDim.x + tid;
    if (gt < BB * N_FULL) {
        __stcs(&g_cnt[gt], 0);
        __stcs(&g_inv[gt], 0);
    }
    __syncthreads();

    const int r    = tid >> 3;               // local row 0..31
    const int q    = tid & 7;                // interleave lane
    const int grow = rowBase + r;            // global output row
    const int row  = srow[r];
    const int b    = grow / N_FULL;

    float4* dst = out + (size_t)grow * 64 + q;

    if (row >= 0) {
        const float4* s = img + ((size_t)b * N_SMALL + row) * 64 + q;
        float4 v0 = __ldg(s + 0 * 8);
        float4 v1 = __ldg(s + 1 * 8);
        float4 v2 = __ldg(s + 2 * 8);
        float4 v3 = __ldg(s + 3 * 8);
        float4 v4 = __ldg(s + 4 * 8);
        float4 v5 = __ldg(s + 5 * 8);
        float4 v6 = __ldg(s + 6 * 8);
        float4 v7 = __ldg(s + 7 * 8);
        __stcs(dst + 0 * 8, v0);
        __stcs(dst + 1 * 8, v1);
        __stcs(dst + 2 * 8, v2);
        __stcs(dst + 3 * 8, v3);
        __stcs(dst + 4 * 8, v4);
        __stcs(dst + 5 * 8, v5);
        __stcs(dst + 6 * 8, v6);
        __stcs(dst + 7 * 8, v7);
    } else {
        const float4 z = make_float4(0.f, 0.f, 0.f, 0.f);
        #pragma unroll
        for (int i = 0; i < 8; i++) __stcs(dst + i * 8, z);
    }
}

extern "C" void kernel_launch(void* const* d_in, const int* in_sizes, int n_in,
                              void* d_out, int out_size)
{
    const float* images   = (const float*)d_in[0];
    const int*   mask_idx = (const int*)d_in[1];
    const int*   order    = (const int*)d_in[2];
    float* out = (float*)d_out;

    const int fill_threads = BB * KK + BB * N_SMALL;   // 131072
    fill_kernel<<<(fill_threads + 255) / 256, 256>>>(mask_idx, order);

    chase_kernel<<<(BB * N_FULL + 255) / 256, 256>>>();

    gather_kernel<<<BB * N_FULL / RPB, 256>>>((const float4*)images, (float4*)out);
}

// round 13
// speedup vs baseline: 1.1102x; 1.0006x over previous
#include <cuda_runtime.h>

#define BB       8
#define N_SMALL  12288
#define N_FULL   24576
#define CC       256
#define KK       4096
#define SLOTS    8             // max writes tracked per vertex (Poisson(1/6))

// Global scratch (~7.6 MB). Zero-initialized at module load == empty state:
//   g_cnt == 0  : no write events bucketed
//   g_inv == 0  : "vertex not in mask" (we store image_row + 1, 0 = absent)
// The LAST kernel (gather) restores this empty state for the next replay.
__device__ int g_cnt  [BB * N_FULL];          // writes per vertex
__device__ int g_slots[BB * N_FULL * SLOTS];  // packed (p<<15)|f, unordered
__device__ int g_inv  [BB * N_FULL];          // full-vertex -> image row + 1, 0 = none
__device__ int g_row  [BB * N_FULL];          // output row -> image row, or -1

// float4 load with L2 evict_last policy (via createpolicy + cache_hint —
// the immediate .L2::evict_last qualifier needs 256-bit loads on ptxas).
// Keeps image rows resident in L2 (read ~2x on average) while the output
// write stream evicts first.
__device__ __forceinline__ float4 ldg_el(const float4* p)
{
    float4 v;
    asm volatile(
        "{\n\t"
        ".reg .b64 pol;\n\t"
        "createpolicy.fractional.L2::evict_last.b64 pol, 1.0;\n\t"
        "ld.global.nc.L2::cache_hint.v4.f32 {%0,%1,%2,%3}, [%4], pol;\n\t"
        "}"
        : "=f"(v.x), "=f"(v.y), "=f"(v.z), "=f"(v.w) : "l"(p));
    return v;
}

// ---------------------------------------------------------------------------
// K1: fill — bucket write events + scatter mask into inv.
//   Reference scan at time p = 0..K-1 executes vf[T[p]] = vf[F[p]] with
//   F[p] = order[b,0,K-1-p], T[p] = order[b,1,K-1-p]. Time order is captured
//   in the packed entries, so processing order here is irrelevant.
// ---------------------------------------------------------------------------
__global__ void fill_kernel(const int* __restrict__ mask_idx,
                            const int* __restrict__ order)
{
    const int t = blockIdx.x * blockDim.x + threadIdx.x;
    if (t < BB * KK) {
        const int b = t / KK;
        const int k = t - b * KK;           // order column; time p = KK-1-k
        const int f = __ldg(&order[b * 2 * KK + k]);
        const int v = __ldg(&order[b * 2 * KK + KK + k]);
        const int idx  = b * N_FULL + v;
        const int slot = atomicAdd(&g_cnt[idx], 1);
        if (slot < SLOTS)                   // overflow prob ~5e-8 per run
            __stcs(&g_slots[idx * SLOTS + slot], ((KK - 1 - k) << 15) | f);
    } else {
        const int u = t - BB * KK;
        if (u < BB * N_SMALL) {
            const int b = u / N_SMALL;
            const int i = u - b * N_SMALL;
            g_inv[b * N_FULL + __ldg(&mask_idx[u])] = i + 1;
        }
    }
}

// ---------------------------------------------------------------------------
// K2: one thread per (b, v) — parallel provenance chase.
//   chase(v, P): among writes to v with time < P pick the latest; hop to its
//   source with the new bound; stop when none. Expected hops ~1.2.
// ---------------------------------------------------------------------------
__global__ void chase_kernel()
{
    const int t = blockIdx.x * blockDim.x + threadIdx.x;
    if (t >= BB * N_FULL) return;
    const int b    = t / N_FULL;
    const int base = b * N_FULL;

    int cur = t - base, P = KK;
    for (;;) {
        const int idx = base + cur;
        const int n   = __ldg(&g_cnt[idx]);
        int best = -1;
        for (int j = 0; j < n; j++) {
            int pv = __ldg(&g_slots[idx * SLOTS + j]);
            if ((pv >> 15) < P && pv > best) best = pv;
        }
        if (best < 0) break;
        cur = best & 0x7FFF;
        P   = best >> 15;
    }
    g_row[t] = __ldg(&g_inv[base + cur]) - 1;   // -1 = zero row
}

// ---------------------------------------------------------------------------
// K3: gather with smem-staged row indices (proven R11 form).
//   CTA = 256 threads owns 32 consecutive output rows (32 KB).
//   Each thread serves ONE row with 8 INDEPENDENT float4 loads, interleaved
//   so each warp instruction touches contiguous 128B lines.
//   Image loads use L2 evict_last hint; output stores stream (evict-first).
//   ALSO restores g_cnt/g_inv empty state for the next graph replay.
// ---------------------------------------------------------------------------
#define RPB 32                               // rows per block

__global__ void __launch_bounds__(256, 4)
gather_kernel(const float4* __restrict__ img,
              float4* __restrict__ out)
{
    __shared__ int srow[RPB];

    const int tid     = threadIdx.x;
    const int rowBase = blockIdx.x * RPB;

    if (tid < RPB) srow[tid] = __ldg(&g_row[rowBase + tid]);

    // restore empty scratch state for the next replay (reads only g_row)
    const int gt = blockIdx.x * blockDim.x + tid;
    if (gt < BB * N_FULL) {
        __stcs(&g_cnt[gt], 0);
        __stcs(&g_inv[gt], 0);
    }
    __syncthreads();

    const int r    = tid >> 3;               // local row 0..31
    const int q    = tid & 7;                // interleave lane
    const int grow = rowBase + r;            // global output row
    const int row  = srow[r];
    const int b    = grow / N_FULL;

    float4* dst = out + (size_t)grow * 64 + q;

    if (row >= 0) {
        const float4* s = img + ((size_t)b * N_SMALL + row) * 64 + q;
        float4 v0 = ldg_el(s + 0 * 8);
        float4 v1 = ldg_el(s + 1 * 8);
        float4 v2 = ldg_el(s + 2 * 8);
        float4 v3 = ldg_el(s + 3 * 8);
        float4 v4 = ldg_el(s + 4 * 8);
        float4 v5 = ldg_el(s + 5 * 8);
        float4 v6 = ldg_el(s + 6 * 8);
        float4 v7 = ldg_el(s + 7 * 8);
        __stcs(dst + 0 * 8, v0);
        __stcs(dst + 1 * 8, v1);
        __stcs(dst + 2 * 8, v2);
        __stcs(dst + 3 * 8, v3);
        __stcs(dst + 4 * 8, v4);
        __stcs(dst + 5 * 8, v5);
        __stcs(dst + 6 * 8, v6);
        __stcs(dst + 7 * 8, v7);
    } else {
        const float4 z = make_float4(0.f, 0.f, 0.f, 0.f);
        #pragma unroll
        for (int i = 0; i < 8; i++) __stcs(dst + i * 8, z);
    }
}

extern "C" void kernel_launch(void* const* d_in, const int* in_sizes, int n_in,
                              void* d_out, int out_size)
{
    const float* images   = (const float*)d_in[0];
    const int*   mask_idx = (const int*)d_in[1];
    const int*   order    = (const int*)d_in[2];
    float* out = (float*)d_out;

    const int fill_threads = BB * KK + BB * N_SMALL;   // 131072
    fill_kernel<<<(fill_threads + 255) / 256, 256>>>(mask_idx, order);

    chase_kernel<<<(BB * N_FULL + 255) / 256, 256>>>();

    gather_kernel<<<BB * N_FULL / RPB, 256>>>((const float4*)images, (float4*)out);
}